// round 2
// baseline (speedup 1.0000x reference)
#include <cuda_runtime.h>
#include <cuda_bf16.h>
#include <cstdint>

// ExpertCapacityBuffer: N tokens, TOP_K=2 slots, 64 experts.
// capacity = ceil(1.25 * N * TOP_K / 64)
// Flat order slot-major: f in [0, 2N), slot = f / N, tok = f % N.
// rank(f) = #{g < f : expert(g) == expert(f)}; keep iff rank < capacity.

#define N_EXPERTS 64
#define BLK 512
#define MAX_BLOCKS 4096

__device__ int g_bc[MAX_BLOCKS * N_EXPERTS];  // per-block expert counts -> prefixes
__device__ int g_is64;                        // 1 if indices are int64, else int32

// Dtype-agnostic expert index load
__device__ __forceinline__ int load_e(const void* p, int i) {
    if (g_is64) return (int)((const long long*)p)[i];
    return ((const int*)p)[i];
}

// ---------------- Kernel 0: detect index dtype ----------------
// int64 values in [0,64) little-endian => every odd 32-bit word is 0.
// 128 odd words all zero for random int32 in [0,64) has prob ~(1/64)^128 ~ 0.
__global__ void k_detect(const unsigned* __restrict__ raw, int n_words) {
    int t = threadIdx.x;                 // 128 threads
    int idx = 2 * t + 1;
    unsigned v = (idx < n_words) ? raw[idx] : 0u;
    unsigned nz = __ballot_sync(0xFFFFFFFFu, v != 0u);
    __shared__ int any_nz;
    if (t == 0) any_nz = 0;
    __syncthreads();
    if (nz && (t % 32 == 0)) atomicOr(&any_nz, 1);
    __syncthreads();
    if (t == 0) g_is64 = any_nz ? 0 : 1;
}

// ---------------- Kernel 1: per-block expert histogram ----------------
__global__ void k_count(const void* __restrict__ eidx, int n_tok, int flat) {
    __shared__ int hist[N_EXPERTS];
    int t = threadIdx.x;
    if (t < N_EXPERTS) hist[t] = 0;
    __syncthreads();

    int f = blockIdx.x * BLK + t;
    if (f < flat) {
        int slot = f / n_tok;
        int tok  = f - slot * n_tok;
        int e = load_e(eidx, tok * 2 + slot) & (N_EXPERTS - 1);
        unsigned am = __activemask();
        unsigned m = __match_any_sync(am, e);
        int lane = t & 31;
        if ((m & ((1u << lane) - 1u)) == 0)          // group leader
            atomicAdd(&hist[e], __popc(m));
    }
    __syncthreads();
    if (t < N_EXPERTS) g_bc[blockIdx.x * N_EXPERTS + t] = hist[t];
}

// ---------------- Kernel 2: exclusive scan over blocks, per expert ----------------
__global__ void k_scan(int nb) {
    int e = threadIdx.x;          // 64 threads
    int run = 0;
    for (int b = 0; b < nb; b++) {
        int c = g_bc[b * N_EXPERTS + e];
        g_bc[b * N_EXPERTS + e] = run;
        run += c;
    }
}

// ---------------- Kernel 3: ranks; write capped weights (+optional indices) ----------------
// idx_mode: 0 = no index output, 1 = write as float, 2 = write as int64
__global__ void k_apply(const float* __restrict__ w,
                        const void* __restrict__ eidx,
                        int n_tok, int flat, int capacity,
                        float* __restrict__ out_w,
                        float* __restrict__ out_idx,
                        int idx_mode) {
    __shared__ int whist[(BLK / 32) * N_EXPERTS];   // 16 warps x 64 experts
    int t = threadIdx.x;
    int warp = t >> 5, lane = t & 31;

    for (int i = t; i < (BLK / 32) * N_EXPERTS; i += BLK) whist[i] = 0;
    __syncthreads();

    int f = blockIdx.x * BLK + t;
    bool valid = f < flat;
    int e = 0, wrank = 0, slot = 0, tok = 0;
    if (valid) {
        slot = f / n_tok;
        tok  = f - slot * n_tok;
        e = load_e(eidx, tok * 2 + slot) & (N_EXPERTS - 1);
        unsigned am = __activemask();
        unsigned m = __match_any_sync(am, e);
        wrank = __popc(m & ((1u << lane) - 1u));
        if (wrank == 0) whist[warp * N_EXPERTS + e] = __popc(m);
    }
    __syncthreads();

    // exclusive scan across the 16 warps, per expert (threads 0..63)
    if (t < N_EXPERTS) {
        int run = 0;
        #pragma unroll
        for (int wv = 0; wv < BLK / 32; wv++) {
            int c = whist[wv * N_EXPERTS + t];
            whist[wv * N_EXPERTS + t] = run;
            run += c;
        }
    }
    __syncthreads();

    if (valid) {
        int rank = g_bc[blockIdx.x * N_EXPERTS + e] + whist[warp * N_EXPERTS + e] + wrank;
        int pos = tok * 2 + slot;
        float wv = w[pos];
        out_w[pos] = (rank < capacity) ? wv : 0.0f;
        if (idx_mode == 1)      out_idx[pos] = (float)e;
        else if (idx_mode == 2) ((long long*)out_idx)[pos] = (long long)e;
    }
}

// ---------------- Kernel 4: per-token overflow mask ----------------
__global__ void k_mask(const float* __restrict__ out_w, int n_tok,
                       float* __restrict__ out_mask) {
    int t = blockIdx.x * blockDim.x + threadIdx.x;
    if (t < n_tok) {
        float2 v = reinterpret_cast<const float2*>(out_w)[t];
        out_mask[t] = ((v.x + v.y) == 0.0f) ? 1.0f : 0.0f;
    }
}

extern "C" void kernel_launch(void* const* d_in, const int* in_sizes, int n_in,
                              void* d_out, int out_size) {
    const float* w    = (const float*)d_in[0];
    const void*  eidx = d_in[1];

    int flat  = in_sizes[0];        // N * TOP_K
    int n_tok = flat / 2;
    int capacity = (flat * 5 + 255) / 256;   // ceil(1.25 * flat / 64)
    if (capacity < 1) capacity = 1;
    int nb = (flat + BLK - 1) / BLK;
    if (nb > MAX_BLOCKS) nb = MAX_BLOCKS;    // (flat=262144 -> nb=512; guard only)

    float* out = (float*)d_out;
    float* out_w    = out;          // weights_capped (N,2) always first
    float* out_idx  = nullptr;
    float* out_mask = nullptr;
    int idx_mode = 0;

    if (out_size >= 3 * flat + n_tok) {
        // weights(f32) + indices(i64, 2 words each) + mask
        idx_mode = 2;
        out_idx  = out + flat;
        out_mask = out + 3 * flat;
    } else if (out_size >= 2 * flat + n_tok) {
        // weights(f32) + indices(one word each) + mask
        idx_mode = 1;
        out_idx  = out + flat;
        out_mask = out + 2 * flat;
    } else if (out_size >= flat + n_tok) {
        out_mask = out + flat;
    }

    k_detect<<<1, 128>>>((const unsigned*)eidx, flat);  // flat >= 256 here
    k_count<<<nb, BLK>>>(eidx, n_tok, flat);
    k_scan<<<1, N_EXPERTS>>>(nb);
    k_apply<<<nb, BLK>>>(w, eidx, n_tok, flat, capacity, out_w, out_idx, idx_mode);
    if (out_mask)
        k_mask<<<(n_tok + 255) / 256, 256>>>(out_w, n_tok, out_mask);
}